// round 3
// baseline (speedup 1.0000x reference)
#include <cuda_runtime.h>
#include <cstdint>

// ----------------------------------------------------------------------------
// ResidualKANBlock fused kernel (fp32, f32x2-packed SIMT baseline)
//
//   kan[n,o] = sum_i silu(x[n,i]) * base_w[o,i]
//            + sum_i sum_{t=0..3} b_t(u_{n,i}) * spline_w[o, i*13 + c_{n,i}-3+t]
//   out = LN(kan)*gamma + beta + x
//
// Uniform grid => basis is a cardinal cubic B-spline: only 4 nonzero coeffs,
// values are closed-form cubics of u. Cell index c is uniform per (token,i),
// so a warp-uniform switch selects register-resident weight rows.
// ----------------------------------------------------------------------------

#define IN_DIM   128
#define OUT_DIM  128
#define NCOEF    13
#define NTOK     65536
#define TOK_PER_CTA 16
#define THREADS  256      // 4 groups of 64 threads; each thread owns an o-pair
#define LN_EPS   1e-5f

// Packed weight layout: g_Wp[(i*64 + q)*16 + j] = {w(2q,i,j), w(2q+1,i,j)}
//   j in [0,12]: spline_w[o, i*13 + j];  j == 13: base_w[o,i];  j = 14,15: 0
__device__ unsigned long long g_Wp[128 * 64 * 16];

struct __align__(16) BS {
    unsigned long long bd[4];  // duplicated basis pair {b_t, b_t}
    unsigned long long sd;     // duplicated silu pair {s, s}
    unsigned int off;          // clamped window start j0 in [0,9]
    unsigned int pad;
};

__device__ __forceinline__ unsigned long long dupf(float v) {
    unsigned int u = __float_as_uint(v);
    return (unsigned long long)u | ((unsigned long long)u << 32);
}

#define FMA2(acc, b, w) \
    asm("fma.rn.f32x2 %0, %1, %2, %0;" : "+l"(acc) : "l"(b), "l"(w))

// ---------------------------------------------------------------- weight prep
__global__ void prep_weights_kernel(const float* __restrict__ base_w,
                                    const float* __restrict__ spline_w) {
    int idx = blockIdx.x * blockDim.x + threadIdx.x;  // 0 .. 131071
    int j = idx & 15;
    int q = (idx >> 4) & 63;
    int i = idx >> 10;
    float v0, v1;
    if (j < NCOEF) {
        v0 = spline_w[(2 * q) * (IN_DIM * NCOEF) + i * NCOEF + j];
        v1 = spline_w[(2 * q + 1) * (IN_DIM * NCOEF) + i * NCOEF + j];
    } else if (j == 13) {
        v0 = base_w[(2 * q) * IN_DIM + i];
        v1 = base_w[(2 * q + 1) * IN_DIM + i];
    } else {
        v0 = 0.f; v1 = 0.f;
    }
    g_Wp[idx] = (unsigned long long)__float_as_uint(v0)
              | ((unsigned long long)__float_as_uint(v1) << 32);
}

// ------------------------------------------------------------------ main fused
__global__ void __launch_bounds__(THREADS, 2)
kan_main_kernel(const float* __restrict__ x,
                const float* __restrict__ gamma,
                const float* __restrict__ beta,
                float* __restrict__ out) {
    extern __shared__ unsigned char smem_raw[];
    BS* bsm = reinterpret_cast<BS*>(smem_raw);                       // [16][128]
    float* redS = reinterpret_cast<float*>(smem_raw + TOK_PER_CTA * IN_DIM * sizeof(BS)); // [8 warps][4 tok]
    float* redQ = redS + 32;

    const int tid = threadIdx.x;
    const int q   = tid & 63;        // o-pair index: outputs 2q, 2q+1
    const int g   = tid >> 6;        // token group 0..3 (4 tokens each)
    const int w2  = (tid >> 5) & 1;  // warp-within-group
    const int tb  = blockIdx.x * TOK_PER_CTA;

    // ---------------- phase 1: silu + cardinal cubic basis -> smem ----------
    #pragma unroll
    for (int ph = 0; ph < (TOK_PER_CTA * IN_DIM) / THREADS; ++ph) {
        int idx = ph * THREADS + tid;
        int tok = idx >> 7;
        int i   = idx & 127;
        float xv = x[(tb + tok) * IN_DIM + i];

        float s = xv / (1.f + __expf(-xv));     // silu

        // t = (x - g0)/h with g0 = -1.6, h = 0.2  ->  t = 5x + 8
        float t5 = fmaf(xv, 5.f, 8.f);
        float cf = floorf(t5);
        int ci = (int)cf;
        float u  = t5 - cf;
        float um = 1.f - u;
        float b0 = um * um * um * (1.f / 6.f);
        float b3 = u * u * u * (1.f / 6.f);
        float b1 = ((3.f * u - 6.f) * u * u + 4.f) * (1.f / 6.f);
        float b2 = (((-3.f * u + 3.f) * u + 3.f) * u + 1.f) * (1.f / 6.f);
        int j0 = ci - 3;
        if (t5 < 0.f || t5 >= 16.f) { b0 = b1 = b2 = b3 = 0.f; j0 = 0; }
        // clamp window into valid coeff range [0,12], zero-filling truncations
        while (j0 < 0) { b0 = b1; b1 = b2; b2 = b3; b3 = 0.f; ++j0; }
        while (j0 > 9) { b3 = b2; b2 = b1; b1 = b0; b0 = 0.f; --j0; }

        BS* e = &bsm[idx];
        e->bd[0] = dupf(b0);
        e->bd[1] = dupf(b1);
        e->bd[2] = dupf(b2);
        e->bd[3] = dupf(b3);
        e->sd    = dupf(s);
        e->off   = (unsigned)j0;
    }
    __syncthreads();

    // ---------------- phase 2: contraction (register weights + switch) ------
    unsigned long long acc[4];
    acc[0] = acc[1] = acc[2] = acc[3] = 0ull;   // {0.f, 0.f} packed

    for (int i = 0; i < IN_DIM; ++i) {
        const ulonglong2* wp = reinterpret_cast<const ulonglong2*>(
            g_Wp + ((size_t)i * 64 + q) * 16);
        unsigned long long w[14];
        #pragma unroll
        for (int jj = 0; jj < 7; ++jj) {
            ulonglong2 v = wp[jj];
            w[2 * jj]     = v.x;
            w[2 * jj + 1] = v.y;
        }
        #pragma unroll
        for (int k = 0; k < 4; ++k) {
            const BS* e = &bsm[(4 * g + k) * IN_DIM + i];
            ulonglong2 b01 = *reinterpret_cast<const ulonglong2*>(&e->bd[0]);
            ulonglong2 b23 = *reinterpret_cast<const ulonglong2*>(&e->bd[2]);
            unsigned long long sd = e->sd;
            unsigned off = e->off;
            FMA2(acc[k], sd, w[13]);
            switch (off) {
            case 0: FMA2(acc[k], b01.x, w[0]); FMA2(acc[k], b01.y, w[1]); FMA2(acc[k], b23.x, w[2]); FMA2(acc[k], b23.y, w[3]); break;
            case 1: FMA2(acc[k], b01.x, w[1]); FMA2(acc[k], b01.y, w[2]); FMA2(acc[k], b23.x, w[3]); FMA2(acc[k], b23.y, w[4]); break;
            case 2: FMA2(acc[k], b01.x, w[2]); FMA2(acc[k], b01.y, w[3]); FMA2(acc[k], b23.x, w[4]); FMA2(acc[k], b23.y, w[5]); break;
            case 3: FMA2(acc[k], b01.x, w[3]); FMA2(acc[k], b01.y, w[4]); FMA2(acc[k], b23.x, w[5]); FMA2(acc[k], b23.y, w[6]); break;
            case 4: FMA2(acc[k], b01.x, w[4]); FMA2(acc[k], b01.y, w[5]); FMA2(acc[k], b23.x, w[6]); FMA2(acc[k], b23.y, w[7]); break;
            case 5: FMA2(acc[k], b01.x, w[5]); FMA2(acc[k], b01.y, w[6]); FMA2(acc[k], b23.x, w[7]); FMA2(acc[k], b23.y, w[8]); break;
            case 6: FMA2(acc[k], b01.x, w[6]); FMA2(acc[k], b01.y, w[7]); FMA2(acc[k], b23.x, w[8]); FMA2(acc[k], b23.y, w[9]); break;
            case 7: FMA2(acc[k], b01.x, w[7]); FMA2(acc[k], b01.y, w[8]); FMA2(acc[k], b23.x, w[9]); FMA2(acc[k], b23.y, w[10]); break;
            case 8: FMA2(acc[k], b01.x, w[8]); FMA2(acc[k], b01.y, w[9]); FMA2(acc[k], b23.x, w[10]); FMA2(acc[k], b23.y, w[11]); break;
            default: FMA2(acc[k], b01.x, w[9]); FMA2(acc[k], b01.y, w[10]); FMA2(acc[k], b23.x, w[11]); FMA2(acc[k], b23.y, w[12]); break;
            }
        }
    }

    // ---------------- phase 3: LayerNorm + residual -------------------------
    float lo[4], hi[4];
    #pragma unroll
    for (int k = 0; k < 4; ++k) {
        unsigned int ulo, uhi;
        asm("mov.b64 {%0, %1}, %2;" : "=r"(ulo), "=r"(uhi) : "l"(acc[k]));
        lo[k] = __uint_as_float(ulo);
        hi[k] = __uint_as_float(uhi);
        float vs = lo[k] + hi[k];
        float vq = lo[k] * lo[k] + hi[k] * hi[k];
        #pragma unroll
        for (int m = 16; m > 0; m >>= 1) {
            vs += __shfl_xor_sync(0xffffffffu, vs, m);
            vq += __shfl_xor_sync(0xffffffffu, vq, m);
        }
        if ((tid & 31) == 0) {
            redS[(g * 2 + w2) * 4 + k] = vs;
            redQ[(g * 2 + w2) * 4 + k] = vq;
        }
    }
    __syncthreads();

    const float2 gq = reinterpret_cast<const float2*>(gamma)[q];
    const float2 bq = reinterpret_cast<const float2*>(beta)[q];
    const float2* x2 = reinterpret_cast<const float2*>(x);
    float2* o2 = reinterpret_cast<float2*>(out);

    #pragma unroll
    for (int k = 0; k < 4; ++k) {
        int tok = tb + 4 * g + k;
        float sum = redS[(g * 2) * 4 + k] + redS[(g * 2 + 1) * 4 + k];
        float sq  = redQ[(g * 2) * 4 + k] + redQ[(g * 2 + 1) * 4 + k];
        float mu  = sum * (1.f / OUT_DIM);
        float var = sq * (1.f / OUT_DIM) - mu * mu;
        float rs  = rsqrtf(var + LN_EPS);
        float2 xv = x2[tok * (OUT_DIM / 2) + q];
        float2 ov;
        ov.x = (lo[k] - mu) * rs * gq.x + bq.x + xv.x;
        ov.y = (hi[k] - mu) * rs * gq.y + bq.y + xv.y;
        o2[tok * (OUT_DIM / 2) + q] = ov;
    }
}

// ---------------------------------------------------------------------- launch
extern "C" void kernel_launch(void* const* d_in, const int* in_sizes, int n_in,
                              void* d_out, int out_size) {
    const float* x        = (const float*)d_in[0];
    // d_in[1] = grid (unused: uniform grid is reproduced analytically)
    const float* base_w   = (const float*)d_in[2];
    const float* spline_w = (const float*)d_in[3];
    const float* gamma    = (const float*)d_in[4];
    const float* beta     = (const float*)d_in[5];
    float* out            = (float*)d_out;

    prep_weights_kernel<<<512, 256>>>(base_w, spline_w);

    const int smem_bytes = TOK_PER_CTA * IN_DIM * (int)sizeof(BS) + 64 * (int)sizeof(float);
    cudaFuncSetAttribute(kan_main_kernel,
                         cudaFuncAttributeMaxDynamicSharedMemorySize, smem_bytes);
    kan_main_kernel<<<NTOK / TOK_PER_CTA, THREADS, smem_bytes>>>(x, gamma, beta, out);
}

// round 6
// speedup vs baseline: 16.3486x; 16.3486x over previous
#include <cuda_runtime.h>
#include <cuda_fp16.h>
#include <cstdint>

// ResidualKANBlock via legacy mma.sync (m16n8k16 f16, f32 accum), W hi+lo fp16.
// A[128tok x 2048] @ W[128out x 2048]^T ; K-slot map per input dim:
//   slots 0..12 = cardinal cubic B-spline coeff window (4-sparse), 13 = silu, 14/15 = 0.
// Then LayerNorm + gamma/beta + residual.
// R5 fix: B operand uses NON-trans ldmatrix ([n][k] smem == B^T row-major already).

#define NTOK   65536
#define TM     128
#define NCTA   (NTOK / TM)
#define NCHUNK 64                    // 2 input dims per chunk (K=32 slots)
#define LN_EPS 1e-5f

#define APITCH 80                    // 32 halves + 16B pad (conflict-free ldmatrix)
#define ABUF   (128 * APITCH)
#define WBUF   (2 * 128 * APITCH)    // hi + lo
#define SM_A0  0
#define SM_A1  ABUF
#define SM_W   (2 * ABUF)            // 3 buffers of WBUF
#define SM_GB  (SM_W + 3 * WBUF)
#define SM_TOT (SM_GB + 1024)

__device__ float          g_xT[128u * 65536u];          // x transposed [dim][token]
__device__ unsigned short g_W[NCHUNK * (WBUF / 2)];     // prebaked padded hi|lo fp16 image

__device__ __forceinline__ unsigned s2u(const void* p) {
    unsigned r;
    asm("{ .reg .u64 t; cvta.to.shared.u64 t, %1; cvt.u32.u64 %0, t; }" : "=r"(r) : "l"(p));
    return r;
}

#define LDSM_X4(r, a) \
    asm volatile("ldmatrix.sync.aligned.m8n8.x4.shared.b16 {%0,%1,%2,%3}, [%4];" \
                 : "=r"((r)[0]), "=r"((r)[1]), "=r"((r)[2]), "=r"((r)[3]) : "r"(a))
#define MMA16816(d, a, b0, b1) \
    asm volatile("mma.sync.aligned.m16n8k16.row.col.f32.f16.f16.f32 " \
                 "{%0,%1,%2,%3}, {%4,%5,%6,%7}, {%8,%9}, {%0,%1,%2,%3};" \
                 : "+f"((d)[0]), "+f"((d)[1]), "+f"((d)[2]), "+f"((d)[3]) \
                 : "r"((a)[0]), "r"((a)[1]), "r"((a)[2]), "r"((a)[3]), "r"(b0), "r"(b1))
#define CPASYNC16(dst, src) \
    asm volatile("cp.async.cg.shared.global [%0], [%1], 16;" :: "r"(dst), "l"(src) : "memory")

// ------------------------------------------------------------- prep kernels
__global__ void transpose_x(const float* __restrict__ x) {
    __shared__ float t[32][33];
    int bx = blockIdx.x * 32, by = blockIdx.y * 32;
    int lx = threadIdx.x, ly = threadIdx.y;
    #pragma unroll
    for (int r = 0; r < 32; r += 8)
        t[ly + r][lx] = x[(size_t)(bx + ly + r) * 128 + by + lx];
    __syncthreads();
    #pragma unroll
    for (int r = 0; r < 32; r += 8)
        g_xT[(size_t)(by + ly + r) * 65536 + bx + lx] = t[lx][ly + r];
}

__global__ void prep_w(const float* __restrict__ base_w,
                       const float* __restrict__ spline_w) {
    int idx = blockIdx.x * blockDim.x + threadIdx.x;   // 0..524287
    int j  = idx & 31;
    int n  = (idx >> 5) & 127;
    int p  = (idx >> 12) & 1;          // 0=hi 1=lo
    int c  = idx >> 13;                // chunk
    int i  = 2 * c + (j >> 4);
    int jj = j & 15;
    float v = 0.f;
    if (jj < 13)       v = spline_w[(size_t)n * 1664 + i * 13 + jj];
    else if (jj == 13) v = base_w[n * 128 + i];
    __half hi = __float2half_rn(v);
    __half o  = p ? __float2half_rn(v - __half2float(hi)) : hi;
    g_W[(size_t)c * (WBUF / 2) + p * 5120 + n * 40 + j] = __half_as_ushort(o);
}

// --------------------------------------------------------------- main kernel
__global__ void __launch_bounds__(256, 2)
kan_mma(const float* __restrict__ x, const float* __restrict__ gamma,
        const float* __restrict__ beta, float* __restrict__ out)
{
    extern __shared__ unsigned char smem[];
    const unsigned sb = s2u(smem);
    const int tid  = threadIdx.x;
    const int w    = tid >> 5;
    const int l    = tid & 31;
    const int tok  = tid & 127;          // A-build token
    const int e    = tid >> 7;           // A-build dim-within-chunk (0/1)
    const int tokbase = blockIdx.x * TM;

    if (tid < 128) {
        float2 gb = make_float2(gamma[tid], beta[tid]);
        *(float2*)(smem + SM_GB + tid * 8) = gb;
    }

    // fragment load addresses (lane-fixed parts)
    const unsigned pa = (unsigned)(w * 16 + (l & 15)) * APITCH + ((l >> 4) & 1) * 16;
    const unsigned pb = (unsigned)(((l >> 4) & 1) * 8 + (l & 7)) * APITCH + ((l >> 3) & 1) * 16;
    const unsigned abo = (unsigned)tok * APITCH + (unsigned)e * 32;

    float acc[16][4];
    #pragma unroll
    for (int t = 0; t < 16; ++t)
        acc[t][0] = acc[t][1] = acc[t][2] = acc[t][3] = 0.f;

    // W prefetch: chunks 0 and 1
    #pragma unroll
    for (int c0 = 0; c0 < 2; ++c0) {
        const unsigned short* src = g_W + (size_t)c0 * (WBUF / 2) + tid * 40;
        unsigned dst = sb + SM_W + c0 * WBUF + tid * 80;
        #pragma unroll
        for (int k = 0; k < 5; ++k) CPASYNC16(dst + 16 * k, (const void*)(src + 8 * k));
        asm volatile("cp.async.commit_group;" ::: "memory");
    }

    const float* xp = g_xT + (size_t)e * 65536 + tokbase + tok;

    for (int c = 0; c < NCHUNK; ++c) {
        const unsigned ab = sb + ((c & 1) ? SM_A1 : SM_A0);
        // ---- build A: this thread -> (tok, dim 2c+e) : 16 fp16 slots ----
        {
            float xv = __ldg(xp + (size_t)(2 * c) * 65536);
            float ex = __expf(-xv);
            float s  = __fdividef(xv, 1.f + ex);            // silu
            float t5 = fmaf(xv, 5.f, 8.f);                  // (x+1.6)/0.2
            float cf = floorf(t5);
            int   ci = (int)cf;
            float u  = t5 - cf;
            float um = 1.f - u;
            float u2 = u * u, um2 = um * um;
            float b0 = um2 * um * (1.f / 6.f);
            float b3 = u2 * u * (1.f / 6.f);
            float b1 = fmaf(u2, fmaf(u, 0.5f, -1.f), 2.f / 3.f);
            float b2 = fmaf(um2, fmaf(um, 0.5f, -1.f), 2.f / 3.f);
            unsigned char* rowb = smem + (ab - sb) + abo;
            uint4 z = make_uint4(0, 0, 0, 0);
            ((uint4*)rowb)[0] = z;
            ((uint4*)rowb)[1] = z;
            unsigned short* row16 = (unsigned short*)rowb;
            row16[13] = __half_as_ushort(__float2half_rn(s));
            int j0 = ci - 3;
            unsigned short h0 = __half_as_ushort(__float2half_rn(b0));
            unsigned short h1 = __half_as_ushort(__float2half_rn(b1));
            unsigned short h2 = __half_as_ushort(__float2half_rn(b2));
            unsigned short h3 = __half_as_ushort(__float2half_rn(b3));
            if ((unsigned)(j0 + 0) <= 12u) row16[j0 + 0] = h0;
            if ((unsigned)(j0 + 1) <= 12u) row16[j0 + 1] = h1;
            if ((unsigned)(j0 + 2) <= 12u) row16[j0 + 2] = h2;
            if ((unsigned)(j0 + 3) <= 12u) row16[j0 + 3] = h3;
        }
        asm volatile("cp.async.wait_group 1;" ::: "memory");   // W(c) resident
        __syncthreads();

        // ---- prefetch W(c+2) ----
        if (c + 2 < NCHUNK) {
            const unsigned short* src = g_W + (size_t)(c + 2) * (WBUF / 2) + tid * 40;
            unsigned dst = sb + SM_W + ((c + 2) % 3) * WBUF + tid * 80;
            #pragma unroll
            for (int k = 0; k < 5; ++k) CPASYNC16(dst + 16 * k, (const void*)(src + 8 * k));
        }
        asm volatile("cp.async.commit_group;" ::: "memory");

        // ---- MMA: K=32 (2 k-steps), hi then lo W ----
        const unsigned wb = sb + SM_W + (c % 3) * WBUF;
        unsigned a0[4], a1[4];
        LDSM_X4(a0, ab + pa);
        LDSM_X4(a1, ab + pa + 32);
        #pragma unroll
        for (int h = 0; h < 2; ++h) {
            const unsigned wbase = wb + h * (WBUF / 2) + pb;
            #pragma unroll
            for (int t = 0; t < 8; ++t) {
                unsigned b[4];
                LDSM_X4(b, wbase + t * (16 * APITCH));           // n0-7/n8-15, k0-15
                MMA16816(acc[2 * t],     a0, b[0], b[1]);
                MMA16816(acc[2 * t + 1], a0, b[2], b[3]);
                LDSM_X4(b, wbase + t * (16 * APITCH) + 32);      // k16-31
                MMA16816(acc[2 * t],     a1, b[0], b[1]);
                MMA16816(acc[2 * t + 1], a1, b[2], b[3]);
            }
        }
    }

    // ---------------- epilogue: LN + gamma/beta + residual -------------------
    float s0 = 0.f, q0 = 0.f, s1 = 0.f, q1 = 0.f;
    #pragma unroll
    for (int t = 0; t < 16; ++t) {
        s0 += acc[t][0] + acc[t][1];
        q0 = fmaf(acc[t][0], acc[t][0], fmaf(acc[t][1], acc[t][1], q0));
        s1 += acc[t][2] + acc[t][3];
        q1 = fmaf(acc[t][2], acc[t][2], fmaf(acc[t][3], acc[t][3], q1));
    }
    #pragma unroll
    for (int m = 1; m <= 2; m <<= 1) {
        s0 += __shfl_xor_sync(0xffffffffu, s0, m);
        q0 += __shfl_xor_sync(0xffffffffu, q0, m);
        s1 += __shfl_xor_sync(0xffffffffu, s1, m);
        q1 += __shfl_xor_sync(0xffffffffu, q1, m);
    }
    float mu0 = s0 * (1.f / 128.f);
    float rs0 = rsqrtf(fmaf(q0, 1.f / 128.f, -mu0 * mu0) + LN_EPS);
    float mu1 = s1 * (1.f / 128.f);
    float rs1 = rsqrtf(fmaf(q1, 1.f / 128.f, -mu1 * mu1) + LN_EPS);

    const int r0 = tokbase + w * 16 + (l >> 2);
    const int r1 = r0 + 8;
    const int qt = l & 3;
    const float* x0 = x + (size_t)r0 * 128;
    const float* x1 = x + (size_t)r1 * 128;
    float* o0 = out + (size_t)r0 * 128;
    float* o1 = out + (size_t)r1 * 128;
    #pragma unroll
    for (int t = 0; t < 16; ++t) {
        int n = 8 * t + qt * 2;
        float4 gb = *(const float4*)(smem + SM_GB + n * 8);   // g[n],b[n],g[n+1],b[n+1]
        float2 xa = *(const float2*)(x0 + n);
        float2 xb = *(const float2*)(x1 + n);
        float2 oa, ob;
        oa.x = fmaf((acc[t][0] - mu0) * rs0, gb.x, gb.y) + xa.x;
        oa.y = fmaf((acc[t][1] - mu0) * rs0, gb.z, gb.w) + xa.y;
        ob.x = fmaf((acc[t][2] - mu1) * rs1, gb.x, gb.y) + xb.x;
        ob.y = fmaf((acc[t][3] - mu1) * rs1, gb.z, gb.w) + xb.y;
        *(float2*)(o0 + n) = oa;
        *(float2*)(o1 + n) = ob;
    }
}

// -------------------------------------------------------------------- launch
extern "C" void kernel_launch(void* const* d_in, const int* in_sizes, int n_in,
                              void* d_out, int out_size) {
    const float* x        = (const float*)d_in[0];
    const float* base_w   = (const float*)d_in[2];
    const float* spline_w = (const float*)d_in[3];
    const float* gamma    = (const float*)d_in[4];
    const float* beta     = (const float*)d_in[5];
    float* out            = (float*)d_out;

    dim3 tb(32, 8);
    transpose_x<<<dim3(2048, 4), tb>>>(x);
    prep_w<<<2048, 256>>>(base_w, spline_w);
    cudaFuncSetAttribute(kan_mma, cudaFuncAttributeMaxDynamicSharedMemorySize, SM_TOT);
    kan_mma<<<NCTA, 256, SM_TOT>>>(x, gamma, beta, out);
}

// round 7
// speedup vs baseline: 17.3901x; 1.0637x over previous
#include <cuda_runtime.h>
#include <cuda_fp16.h>
#include <cstdint>

// ResidualKANBlock via mma.sync (m16n8k16 f16, f32 accum), W hi+lo fp16.
// R6: software-pipelined A-build (build chunk c+1 after MMA(c); x LDG distance 2).

#define NTOK   65536
#define TM     128
#define NCTA   (NTOK / TM)
#define NCHUNK 64                    // 2 input dims per chunk (K=32 slots)
#define LN_EPS 1e-5f

#define APITCH 80                    // 32 halves + 16B pad (conflict-free ldmatrix)
#define ABUF   (128 * APITCH)
#define WBUF   (2 * 128 * APITCH)    // hi + lo
#define SM_A0  0
#define SM_A1  ABUF
#define SM_W   (2 * ABUF)            // 3 buffers of WBUF
#define SM_GB  (SM_W + 3 * WBUF)
#define SM_TOT (SM_GB + 1024)

__device__ float          g_xT[128u * 65536u];          // x transposed [dim][token]
__device__ unsigned short g_W[NCHUNK * (WBUF / 2)];     // prebaked padded hi|lo fp16 image

__device__ __forceinline__ unsigned s2u(const void* p) {
    unsigned r;
    asm("{ .reg .u64 t; cvta.to.shared.u64 t, %1; cvt.u32.u64 %0, t; }" : "=r"(r) : "l"(p));
    return r;
}

#define LDSM_X4(r, a) \
    asm volatile("ldmatrix.sync.aligned.m8n8.x4.shared.b16 {%0,%1,%2,%3}, [%4];" \
                 : "=r"((r)[0]), "=r"((r)[1]), "=r"((r)[2]), "=r"((r)[3]) : "r"(a))
#define MMA16816(d, a, b0, b1) \
    asm volatile("mma.sync.aligned.m16n8k16.row.col.f32.f16.f16.f32 " \
                 "{%0,%1,%2,%3}, {%4,%5,%6,%7}, {%8,%9}, {%0,%1,%2,%3};" \
                 : "+f"((d)[0]), "+f"((d)[1]), "+f"((d)[2]), "+f"((d)[3]) \
                 : "r"((a)[0]), "r"((a)[1]), "r"((a)[2]), "r"((a)[3]), "r"(b0), "r"(b1))
#define CPASYNC16(dst, src) \
    asm volatile("cp.async.cg.shared.global [%0], [%1], 16;" :: "r"(dst), "l"(src) : "memory")

// ------------------------------------------------------------- prep kernels
__global__ void transpose_x(const float* __restrict__ x) {
    __shared__ float t[32][33];
    int bx = blockIdx.x * 32, by = blockIdx.y * 32;
    int lx = threadIdx.x, ly = threadIdx.y;
    #pragma unroll
    for (int r = 0; r < 32; r += 8)
        t[ly + r][lx] = x[(size_t)(bx + ly + r) * 128 + by + lx];
    __syncthreads();
    #pragma unroll
    for (int r = 0; r < 32; r += 8)
        g_xT[(size_t)(by + ly + r) * 65536 + bx + lx] = t[lx][ly + r];
}

__global__ void prep_w(const float* __restrict__ base_w,
                       const float* __restrict__ spline_w) {
    int idx = blockIdx.x * blockDim.x + threadIdx.x;   // 0..524287
    int j  = idx & 31;
    int n  = (idx >> 5) & 127;
    int p  = (idx >> 12) & 1;          // 0=hi 1=lo
    int c  = idx >> 13;                // chunk
    int i  = 2 * c + (j >> 4);
    int jj = j & 15;
    float v = 0.f;
    if (jj < 13)       v = spline_w[(size_t)n * 1664 + i * 13 + jj];
    else if (jj == 13) v = base_w[n * 128 + i];
    __half hi = __float2half_rn(v);
    __half o  = p ? __float2half_rn(v - __half2float(hi)) : hi;
    g_W[(size_t)c * (WBUF / 2) + p * 5120 + n * 40 + j] = __half_as_ushort(o);
}

// --------------------------------------------------------------- main kernel
__global__ void __launch_bounds__(256, 2)
kan_mma(const float* __restrict__ x, const float* __restrict__ gamma,
        const float* __restrict__ beta, float* __restrict__ out)
{
    extern __shared__ unsigned char smem[];
    const unsigned sb = s2u(smem);
    const int tid  = threadIdx.x;
    const int w    = tid >> 5;
    const int l    = tid & 31;
    const int tok  = tid & 127;          // A-build token
    const int e    = tid >> 7;           // A-build dim-within-chunk (0/1)
    const int tokbase = blockIdx.x * TM;

    if (tid < 128) {
        float2 gb = make_float2(gamma[tid], beta[tid]);
        *(float2*)(smem + SM_GB + tid * 8) = gb;
    }

    const unsigned pa = (unsigned)(w * 16 + (l & 15)) * APITCH + ((l >> 4) & 1) * 16;
    const unsigned pb = (unsigned)(((l >> 4) & 1) * 8 + (l & 7)) * APITCH + ((l >> 3) & 1) * 16;
    const unsigned abo = (unsigned)tok * APITCH + (unsigned)e * 32;

    float acc[16][4];
    #pragma unroll
    for (int t = 0; t < 16; ++t)
        acc[t][0] = acc[t][1] = acc[t][2] = acc[t][3] = 0.f;

    // W prefetch: chunks 0 and 1
    #pragma unroll
    for (int c0 = 0; c0 < 2; ++c0) {
        const unsigned short* src = g_W + (size_t)c0 * (WBUF / 2) + tid * 40;
        unsigned dst = sb + SM_W + c0 * WBUF + tid * 80;
        #pragma unroll
        for (int k = 0; k < 5; ++k) CPASYNC16(dst + 16 * k, (const void*)(src + 8 * k));
        asm volatile("cp.async.commit_group;" ::: "memory");
    }

    const float* xp = g_xT + (size_t)e * 65536 + tokbase + tok;

    // A-build as lambda-style macro-free helper (inlined)
    auto buildA = [&](unsigned abuf_off, float xv) {
        float ex = __expf(-xv);
        float s  = __fdividef(xv, 1.f + ex);            // silu
        float t5 = fmaf(xv, 5.f, 8.f);                  // (x+1.6)/0.2
        float cf = floorf(t5);
        int   ci = (int)cf;
        float u  = t5 - cf;
        float um = 1.f - u;
        float u2 = u * u, um2 = um * um;
        float b0 = um2 * um * (1.f / 6.f);
        float b3 = u2 * u * (1.f / 6.f);
        float b1 = fmaf(u2, fmaf(u, 0.5f, -1.f), 2.f / 3.f);
        float b2 = fmaf(um2, fmaf(um, 0.5f, -1.f), 2.f / 3.f);
        unsigned char* rowb = smem + abuf_off + abo;
        uint4 z = make_uint4(0, 0, 0, 0);
        ((uint4*)rowb)[0] = z;
        ((uint4*)rowb)[1] = z;
        unsigned short* row16 = (unsigned short*)rowb;
        row16[13] = __half_as_ushort(__float2half_rn(s));
        int j0 = ci - 3;
        unsigned short h0 = __half_as_ushort(__float2half_rn(b0));
        unsigned short h1 = __half_as_ushort(__float2half_rn(b1));
        unsigned short h2 = __half_as_ushort(__float2half_rn(b2));
        unsigned short h3 = __half_as_ushort(__float2half_rn(b3));
        if ((unsigned)(j0 + 0) <= 12u) row16[j0 + 0] = h0;
        if ((unsigned)(j0 + 1) <= 12u) row16[j0 + 1] = h1;
        if ((unsigned)(j0 + 2) <= 12u) row16[j0 + 2] = h2;
        if ((unsigned)(j0 + 3) <= 12u) row16[j0 + 3] = h3;
    };

    // prologue: build A(0); start x pipeline for chunk 1
    float xv_nxt;
    {
        float xv0 = __ldg(xp);
        buildA(SM_A0, xv0);
        xv_nxt = __ldg(xp + 2u * 65536u);
    }

    for (int c = 0; c < NCHUNK; ++c) {
        const unsigned ab = sb + ((c & 1) ? SM_A1 : SM_A0);

        asm volatile("cp.async.wait_group 1;" ::: "memory");   // W(c) resident
        __syncthreads();                                       // A(c) + W(c) visible

        // prefetch W(c+2)
        if (c + 2 < NCHUNK) {
            const unsigned short* src = g_W + (size_t)(c + 2) * (WBUF / 2) + tid * 40;
            unsigned dst = sb + SM_W + ((c + 2) % 3) * WBUF + tid * 80;
            #pragma unroll
            for (int k = 0; k < 5; ++k) CPASYNC16(dst + 16 * k, (const void*)(src + 8 * k));
        }
        asm volatile("cp.async.commit_group;" ::: "memory");

        // ---- MMA(c): K=32 (2 k-steps), hi then lo W ----
        const unsigned wb = sb + SM_W + (c % 3) * WBUF;
        unsigned a0[4], a1[4];
        LDSM_X4(a0, ab + pa);
        LDSM_X4(a1, ab + pa + 32);
        #pragma unroll
        for (int h = 0; h < 2; ++h) {
            const unsigned wbase = wb + h * (WBUF / 2) + pb;
            #pragma unroll
            for (int t = 0; t < 8; ++t) {
                unsigned b[4];
                LDSM_X4(b, wbase + t * (16 * APITCH));
                MMA16816(acc[2 * t],     a0, b[0], b[1]);
                MMA16816(acc[2 * t + 1], a0, b[2], b[3]);
                LDSM_X4(b, wbase + t * (16 * APITCH) + 32);
                MMA16816(acc[2 * t],     a1, b[0], b[1]);
                MMA16816(acc[2 * t + 1], a1, b[2], b[3]);
            }
        }

        // ---- issue x load for chunk c+2, then build A(c+1) (overlaps MMA) ----
        float xv2 = 0.f;
        if (c + 2 < NCHUNK) xv2 = __ldg(xp + (size_t)(2 * (c + 2)) * 65536u);
        if (c + 1 < NCHUNK)
            buildA(((c + 1) & 1) ? SM_A1 : SM_A0, xv_nxt);
        xv_nxt = xv2;
    }

    // ---------------- epilogue: LN + gamma/beta + residual -------------------
    float s0 = 0.f, q0 = 0.f, s1 = 0.f, q1 = 0.f;
    #pragma unroll
    for (int t = 0; t < 16; ++t) {
        s0 += acc[t][0] + acc[t][1];
        q0 = fmaf(acc[t][0], acc[t][0], fmaf(acc[t][1], acc[t][1], q0));
        s1 += acc[t][2] + acc[t][3];
        q1 = fmaf(acc[t][2], acc[t][2], fmaf(acc[t][3], acc[t][3], q1));
    }
    #pragma unroll
    for (int m = 1; m <= 2; m <<= 1) {
        s0 += __shfl_xor_sync(0xffffffffu, s0, m);
        q0 += __shfl_xor_sync(0xffffffffu, q0, m);
        s1 += __shfl_xor_sync(0xffffffffu, s1, m);
        q1 += __shfl_xor_sync(0xffffffffu, q1, m);
    }
    float mu0 = s0 * (1.f / 128.f);
    float rs0 = rsqrtf(fmaf(q0, 1.f / 128.f, -mu0 * mu0) + LN_EPS);
    float mu1 = s1 * (1.f / 128.f);
    float rs1 = rsqrtf(fmaf(q1, 1.f / 128.f, -mu1 * mu1) + LN_EPS);

    const int r0 = tokbase + w * 16 + (l >> 2);
    const int r1 = r0 + 8;
    const int qt = l & 3;
    const float* x0 = x + (size_t)r0 * 128;
    const float* x1 = x + (size_t)r1 * 128;
    float* o0 = out + (size_t)r0 * 128;
    float* o1 = out + (size_t)r1 * 128;
    #pragma unroll
    for (int t = 0; t < 16; ++t) {
        int n = 8 * t + qt * 2;
        float4 gb = *(const float4*)(smem + SM_GB + n * 8);   // g[n],b[n],g[n+1],b[n+1]
        float2 xa = *(const float2*)(x0 + n);
        float2 xb = *(const float2*)(x1 + n);
        float2 oa, ob;
        oa.x = fmaf((acc[t][0] - mu0) * rs0, gb.x, gb.y) + xa.x;
        oa.y = fmaf((acc[t][1] - mu0) * rs0, gb.z, gb.w) + xa.y;
        ob.x = fmaf((acc[t][2] - mu1) * rs1, gb.x, gb.y) + xb.x;
        ob.y = fmaf((acc[t][3] - mu1) * rs1, gb.z, gb.w) + xb.y;
        *(float2*)(o0 + n) = oa;
        *(float2*)(o1 + n) = ob;
    }
}

// -------------------------------------------------------------------- launch
extern "C" void kernel_launch(void* const* d_in, const int* in_sizes, int n_in,
                              void* d_out, int out_size) {
    const float* x        = (const float*)d_in[0];
    const float* base_w   = (const float*)d_in[2];
    const float* spline_w = (const float*)d_in[3];
    const float* gamma    = (const float*)d_in[4];
    const float* beta     = (const float*)d_in[5];
    float* out            = (float*)d_out;

    dim3 tb(32, 8);
    transpose_x<<<dim3(2048, 4), tb>>>(x);
    prep_w<<<2048, 256>>>(base_w, spline_w);
    cudaFuncSetAttribute(kan_mma, cudaFuncAttributeMaxDynamicSharedMemorySize, SM_TOT);
    kan_mma<<<NCTA, 256, SM_TOT>>>(x, gamma, beta, out);
}

// round 8
// speedup vs baseline: 30.1421x; 1.7333x over previous
#include <cuda_runtime.h>
#include <cuda_fp16.h>
#include <cstdint>

// ResidualKANBlock via mma.sync (m16n8k16 f16, f32 accum).
// R7: W hi-only (fp16) — halves HMMA + LDSM + W traffic; error budget allows it.

#define NTOK   65536
#define TM     128
#define NCTA   (NTOK / TM)
#define NCHUNK 64                    // 2 input dims per chunk (K=32 slots)
#define LN_EPS 1e-5f

#define APITCH 80                    // 32 halves + 16B pad (conflict-free ldmatrix)
#define ABUF   (128 * APITCH)
#define WBUF   (128 * APITCH)        // hi only: 10240 B
#define SM_A0  0
#define SM_A1  ABUF
#define SM_W   (2 * ABUF)            // 3 buffers of WBUF
#define SM_GB  (SM_W + 3 * WBUF)
#define SM_TOT (SM_GB + 1024)

__device__ float          g_xT[128u * 65536u];          // x transposed [dim][token]
__device__ unsigned short g_W[NCHUNK * (WBUF / 2)];     // prebaked padded fp16 image

__device__ __forceinline__ unsigned s2u(const void* p) {
    unsigned r;
    asm("{ .reg .u64 t; cvta.to.shared.u64 t, %1; cvt.u32.u64 %0, t; }" : "=r"(r) : "l"(p));
    return r;
}

#define LDSM_X4(r, a) \
    asm volatile("ldmatrix.sync.aligned.m8n8.x4.shared.b16 {%0,%1,%2,%3}, [%4];" \
                 : "=r"((r)[0]), "=r"((r)[1]), "=r"((r)[2]), "=r"((r)[3]) : "r"(a))
#define MMA16816(d, a, b0, b1) \
    asm volatile("mma.sync.aligned.m16n8k16.row.col.f32.f16.f16.f32 " \
                 "{%0,%1,%2,%3}, {%4,%5,%6,%7}, {%8,%9}, {%0,%1,%2,%3};" \
                 : "+f"((d)[0]), "+f"((d)[1]), "+f"((d)[2]), "+f"((d)[3]) \
                 : "r"((a)[0]), "r"((a)[1]), "r"((a)[2]), "r"((a)[3]), "r"(b0), "r"(b1))
#define CPASYNC16(dst, src) \
    asm volatile("cp.async.cg.shared.global [%0], [%1], 16;" :: "r"(dst), "l"(src) : "memory")

// ------------------------------------------------------------- prep kernels
__global__ void transpose_x(const float* __restrict__ x) {
    __shared__ float t[32][33];
    int bx = blockIdx.x * 32, by = blockIdx.y * 32;
    int lx = threadIdx.x, ly = threadIdx.y;
    #pragma unroll
    for (int r = 0; r < 32; r += 8)
        t[ly + r][lx] = x[(size_t)(bx + ly + r) * 128 + by + lx];
    __syncthreads();
    #pragma unroll
    for (int r = 0; r < 32; r += 8)
        g_xT[(size_t)(by + ly + r) * 65536 + bx + lx] = t[lx][ly + r];
}

__global__ void prep_w(const float* __restrict__ base_w,
                       const float* __restrict__ spline_w) {
    int idx = blockIdx.x * blockDim.x + threadIdx.x;   // 0..262143
    int j  = idx & 31;
    int n  = (idx >> 5) & 127;
    int c  = idx >> 12;                // chunk
    int i  = 2 * c + (j >> 4);
    int jj = j & 15;
    float v = 0.f;
    if (jj < 13)       v = spline_w[(size_t)n * 1664 + i * 13 + jj];
    else if (jj == 13) v = base_w[n * 128 + i];
    g_W[(size_t)c * (WBUF / 2) + n * 40 + j] = __half_as_ushort(__float2half_rn(v));
}

// --------------------------------------------------------------- main kernel
__global__ void __launch_bounds__(256, 2)
kan_mma(const float* __restrict__ x, const float* __restrict__ gamma,
        const float* __restrict__ beta, float* __restrict__ out)
{
    extern __shared__ unsigned char smem[];
    const unsigned sb = s2u(smem);
    const int tid  = threadIdx.x;
    const int w    = tid >> 5;
    const int l    = tid & 31;
    const int tok  = tid & 127;          // A-build token
    const int e    = tid >> 7;           // A-build dim-within-chunk (0/1)
    const int tokbase = blockIdx.x * TM;

    if (tid < 128) {
        float2 gb = make_float2(gamma[tid], beta[tid]);
        *(float2*)(smem + SM_GB + tid * 8) = gb;
    }

    const unsigned pa = (unsigned)(w * 16 + (l & 15)) * APITCH + ((l >> 4) & 1) * 16;
    const unsigned pb = (unsigned)(((l >> 4) & 1) * 8 + (l & 7)) * APITCH + ((l >> 3) & 1) * 16;
    const unsigned abo = (unsigned)tok * APITCH + (unsigned)e * 32;

    float acc[16][4];
    #pragma unroll
    for (int t = 0; t < 16; ++t)
        acc[t][0] = acc[t][1] = acc[t][2] = acc[t][3] = 0.f;

    // W prefetch: chunks 0 and 1 (128 threads x 80B each)
    #pragma unroll
    for (int c0 = 0; c0 < 2; ++c0) {
        if (tid < 128) {
            const unsigned short* src = g_W + (size_t)c0 * (WBUF / 2) + tid * 40;
            unsigned dst = sb + SM_W + c0 * WBUF + tid * 80;
            #pragma unroll
            for (int k = 0; k < 5; ++k) CPASYNC16(dst + 16 * k, (const void*)(src + 8 * k));
        }
        asm volatile("cp.async.commit_group;" ::: "memory");
    }

    const float* xp = g_xT + (size_t)e * 65536 + tokbase + tok;

    auto buildA = [&](unsigned abuf_off, float xv) {
        float ex = __expf(-xv);
        float s  = __fdividef(xv, 1.f + ex);            // silu
        float t5 = fmaf(xv, 5.f, 8.f);                  // (x+1.6)/0.2
        float cf = floorf(t5);
        int   ci = (int)cf;
        float u  = t5 - cf;
        float um = 1.f - u;
        float u2 = u * u, um2 = um * um;
        float b0 = um2 * um * (1.f / 6.f);
        float b3 = u2 * u * (1.f / 6.f);
        float b1 = fmaf(u2, fmaf(u, 0.5f, -1.f), 2.f / 3.f);
        float b2 = fmaf(um2, fmaf(um, 0.5f, -1.f), 2.f / 3.f);
        unsigned char* rowb = smem + abuf_off + abo;
        uint4 z = make_uint4(0, 0, 0, 0);
        ((uint4*)rowb)[0] = z;
        ((uint4*)rowb)[1] = z;
        unsigned short* row16 = (unsigned short*)rowb;
        row16[13] = __half_as_ushort(__float2half_rn(s));
        int j0 = ci - 3;
        unsigned short h0 = __half_as_ushort(__float2half_rn(b0));
        unsigned short h1 = __half_as_ushort(__float2half_rn(b1));
        unsigned short h2 = __half_as_ushort(__float2half_rn(b2));
        unsigned short h3 = __half_as_ushort(__float2half_rn(b3));
        if ((unsigned)(j0 + 0) <= 12u) row16[j0 + 0] = h0;
        if ((unsigned)(j0 + 1) <= 12u) row16[j0 + 1] = h1;
        if ((unsigned)(j0 + 2) <= 12u) row16[j0 + 2] = h2;
        if ((unsigned)(j0 + 3) <= 12u) row16[j0 + 3] = h3;
    };

    // prologue: build A(0); start x pipeline for chunk 1
    float xv_nxt;
    {
        float xv0 = __ldg(xp);
        buildA(SM_A0, xv0);
        xv_nxt = __ldg(xp + 2u * 65536u);
    }

    for (int c = 0; c < NCHUNK; ++c) {
        const unsigned ab = sb + ((c & 1) ? SM_A1 : SM_A0);

        asm volatile("cp.async.wait_group 1;" ::: "memory");   // W(c) resident
        __syncthreads();                                       // A(c) + W(c) visible

        // prefetch W(c+2)
        if (c + 2 < NCHUNK && tid < 128) {
            const unsigned short* src = g_W + (size_t)(c + 2) * (WBUF / 2) + tid * 40;
            unsigned dst = sb + SM_W + ((c + 2) % 3) * WBUF + tid * 80;
            #pragma unroll
            for (int k = 0; k < 5; ++k) CPASYNC16(dst + 16 * k, (const void*)(src + 8 * k));
        }
        asm volatile("cp.async.commit_group;" ::: "memory");

        // ---- MMA(c): K=32 (2 k-steps) ----
        const unsigned wb = sb + SM_W + (c % 3) * WBUF;
        unsigned a0[4], a1[4];
        LDSM_X4(a0, ab + pa);
        LDSM_X4(a1, ab + pa + 32);
        {
            const unsigned wbase = wb + pb;
            #pragma unroll
            for (int t = 0; t < 8; ++t) {
                unsigned b[4];
                LDSM_X4(b, wbase + t * (16 * APITCH));
                MMA16816(acc[2 * t],     a0, b[0], b[1]);
                MMA16816(acc[2 * t + 1], a0, b[2], b[3]);
                LDSM_X4(b, wbase + t * (16 * APITCH) + 32);
                MMA16816(acc[2 * t],     a1, b[0], b[1]);
                MMA16816(acc[2 * t + 1], a1, b[2], b[3]);
            }
        }

        // ---- issue x load for chunk c+2, then build A(c+1) (overlaps MMA) ----
        float xv2 = 0.f;
        if (c + 2 < NCHUNK) xv2 = __ldg(xp + (size_t)(2 * (c + 2)) * 65536u);
        if (c + 1 < NCHUNK)
            buildA(((c + 1) & 1) ? SM_A1 : SM_A0, xv_nxt);
        xv_nxt = xv2;
    }

    // ---------------- epilogue: LN + gamma/beta + residual -------------------
    float s0 = 0.f, q0 = 0.f, s1 = 0.f, q1 = 0.f;
    #pragma unroll
    for (int t = 0; t < 16; ++t) {
        s0 += acc[t][0] + acc[t][1];
        q0 = fmaf(acc[t][0], acc[t][0], fmaf(acc[t][1], acc[t][1], q0));
        s1 += acc[t][2] + acc[t][3];
        q1 = fmaf(acc[t][2], acc[t][2], fmaf(acc[t][3], acc[t][3], q1));
    }
    #pragma unroll
    for (int m = 1; m <= 2; m <<= 1) {
        s0 += __shfl_xor_sync(0xffffffffu, s0, m);
        q0 += __shfl_xor_sync(0xffffffffu, q0, m);
        s1 += __shfl_xor_sync(0xffffffffu, s1, m);
        q1 += __shfl_xor_sync(0xffffffffu, q1, m);
    }
    float mu0 = s0 * (1.f / 128.f);
    float rs0 = rsqrtf(fmaf(q0, 1.f / 128.f, -mu0 * mu0) + LN_EPS);
    float mu1 = s1 * (1.f / 128.f);
    float rs1 = rsqrtf(fmaf(q1, 1.f / 128.f, -mu1 * mu1) + LN_EPS);

    const int r0 = tokbase + w * 16 + (l >> 2);
    const int r1 = r0 + 8;
    const int qt = l & 3;
    const float* x0 = x + (size_t)r0 * 128;
    const float* x1 = x + (size_t)r1 * 128;
    float* o0 = out + (size_t)r0 * 128;
    float* o1 = out + (size_t)r1 * 128;
    #pragma unroll
    for (int t = 0; t < 16; ++t) {
        int n = 8 * t + qt * 2;
        float4 gb = *(const float4*)(smem + SM_GB + n * 8);   // g[n],b[n],g[n+1],b[n+1]
        float2 xa = *(const float2*)(x0 + n);
        float2 xb = *(const float2*)(x1 + n);
        float2 oa, ob;
        oa.x = fmaf((acc[t][0] - mu0) * rs0, gb.x, gb.y) + xa.x;
        oa.y = fmaf((acc[t][1] - mu0) * rs0, gb.z, gb.w) + xa.y;
        ob.x = fmaf((acc[t][2] - mu1) * rs1, gb.x, gb.y) + xb.x;
        ob.y = fmaf((acc[t][3] - mu1) * rs1, gb.z, gb.w) + xb.y;
        *(float2*)(o0 + n) = oa;
        *(float2*)(o1 + n) = ob;
    }
}

// -------------------------------------------------------------------- launch
extern "C" void kernel_launch(void* const* d_in, const int* in_sizes, int n_in,
                              void* d_out, int out_size) {
    const float* x        = (const float*)d_in[0];
    const float* base_w   = (const float*)d_in[2];
    const float* spline_w = (const float*)d_in[3];
    const float* gamma    = (const float*)d_in[4];
    const float* beta     = (const float*)d_in[5];
    float* out            = (float*)d_out;

    dim3 tb(32, 8);
    transpose_x<<<dim3(2048, 4), tb>>>(x);
    prep_w<<<1024, 256>>>(base_w, spline_w);
    cudaFuncSetAttribute(kan_mma, cudaFuncAttributeMaxDynamicSharedMemorySize, SM_TOT);
    kan_mma<<<NCTA, 256, SM_TOT>>>(x, gamma, beta, out);
}

// round 11
// speedup vs baseline: 39.9190x; 1.3244x over previous
#include <cuda_runtime.h>
#include <cuda_fp16.h>
#include <cstdint>

// ResidualKANBlock via mma.sync (m16n8k16 f16, f32 accum).
// R10: R8 design with PITCH=240 (16B-aligned rows for ldmatrix; bank-safe).
//   dense K=1792 (14 slots/dim, 8-dim chunks of K=112), warp n-split (TM=64),
//   16 chunks, W double-buffer cp.async.

#define NTOK   65536
#define TM     64
#define NCTA   (NTOK / TM)            // 1024
#define NCHUNK 16                     // 8 input dims per chunk (K=112 slots)
#define LN_EPS 1e-5f

#define PITCH  240                    // bytes/row: 112 halves data + pad; 16B-aligned
#define ABUF   (64 * PITCH)           // 15360
#define WBUF   (128 * PITCH)          // 30720
#define SM_A0  0
#define SM_A1  ABUF
#define SM_W   (2 * ABUF)             // 2 W buffers
#define SM_GB  (SM_W + 2 * WBUF)
#define SM_EPI (SM_GB + 1024)
#define SM_TOT (SM_EPI + 1024)        // ~94.2 KB -> occupancy 2

__device__ float          g_xT[128u * 65536u];            // x transposed [dim][token]
__device__ unsigned short g_W[NCHUNK * 128 * (PITCH/2)];  // per-chunk padded fp16 image

__device__ __forceinline__ unsigned s2u(const void* p) {
    unsigned r;
    asm("{ .reg .u64 t; cvta.to.shared.u64 t, %1; cvt.u32.u64 %0, t; }" : "=r"(r) : "l"(p));
    return r;
}

#define LDSM_X4(r, a) \
    asm volatile("ldmatrix.sync.aligned.m8n8.x4.shared.b16 {%0,%1,%2,%3}, [%4];" \
                 : "=r"((r)[0]), "=r"((r)[1]), "=r"((r)[2]), "=r"((r)[3]) : "r"(a))
#define MMA16816(d, a, b0, b1) \
    asm volatile("mma.sync.aligned.m16n8k16.row.col.f32.f16.f16.f32 " \
                 "{%0,%1,%2,%3}, {%4,%5,%6,%7}, {%8,%9}, {%0,%1,%2,%3};" \
                 : "+f"((d)[0]), "+f"((d)[1]), "+f"((d)[2]), "+f"((d)[3]) \
                 : "r"((a)[0]), "r"((a)[1]), "r"((a)[2]), "r"((a)[3]), "r"(b0), "r"(b1))
#define CPASYNC16(dst, src) \
    asm volatile("cp.async.cg.shared.global [%0], [%1], 16;" :: "r"(dst), "l"(src) : "memory")

// ------------------------------------------------------------- prep kernels
__global__ void transpose_x(const float* __restrict__ x) {
    __shared__ float t[32][33];
    int bx = blockIdx.x * 32, by = blockIdx.y * 32;
    int lx = threadIdx.x, ly = threadIdx.y;
    #pragma unroll
    for (int r = 0; r < 32; r += 8)
        t[ly + r][lx] = x[(size_t)(bx + ly + r) * 128 + by + lx];
    __syncthreads();
    #pragma unroll
    for (int r = 0; r < 32; r += 8)
        g_xT[(size_t)(by + ly + r) * 65536 + bx + lx] = t[lx][ly + r];
}

__global__ void prep_w(const float* __restrict__ base_w,
                       const float* __restrict__ spline_w) {
    int idx = blockIdx.x * blockDim.x + threadIdx.x;
    if (idx >= NCHUNK * 128 * (PITCH / 2)) return;
    int c = idx / (128 * (PITCH / 2));
    int r = idx % (128 * (PITCH / 2));
    int n = r / (PITCH / 2);
    int s = r % (PITCH / 2);           // slot in row (0..119; 112 live)
    float v = 0.f;
    if (s < 112) {
        int d = s / 14;                // dim in chunk 0..7
        int jj = s - d * 14;           // 0..13
        int i = 8 * c + d;             // global input dim
        if (jj < 13) v = spline_w[(size_t)n * 1664 + i * 13 + jj];
        else         v = base_w[n * 128 + i];
    }
    g_W[(size_t)c * (128 * (PITCH/2)) + n * (PITCH/2) + s] =
        __half_as_ushort(__float2half_rn(v));
}

// --------------------------------------------------------------- main kernel
__global__ void __launch_bounds__(256, 2)
kan_mma(const float* __restrict__ x, const float* __restrict__ gamma,
        const float* __restrict__ beta, float* __restrict__ out)
{
    extern __shared__ unsigned char smem[];
    const unsigned sb = s2u(smem);
    const int tid = threadIdx.x;
    const int w = tid >> 5, l = tid & 31;
    const int g = w >> 1, h = w & 1;            // token group / n-half
    const int tok = tid & 63, p = tid >> 6;     // A-build: token, dim-class
    const int tokbase = blockIdx.x * TM;

    if (tid < 128) {
        float2 gb = make_float2(gamma[tid], beta[tid]);
        *(float2*)(smem + SM_GB + tid * 8) = gb;
    }

    const unsigned paBase = (unsigned)(g * 16 + (l & 15)) * PITCH + ((l >> 4) & 1) * 16;
    const unsigned pbBase = (unsigned)(((l >> 4) & 1) * 8 + (l & 7)) * PITCH + ((l >> 3) & 1) * 16;
    const unsigned hOff = (unsigned)h * 64 * PITCH;

    float acc[8][4];
    #pragma unroll
    for (int t = 0; t < 8; ++t)
        acc[t][0] = acc[t][1] = acc[t][2] = acc[t][3] = 0.f;

    auto cpW = [&](int c, int buf) {
        const char* src = (const char*)(g_W + (size_t)c * (128 * (PITCH/2)));
        unsigned dst = sb + SM_W + buf * WBUF;
        #pragma unroll
        for (int k = 0; k < 8; ++k) {
            int i16 = tid + 256 * k;
            if (i16 < WBUF / 16) CPASYNC16(dst + 16 * i16, src + 16 * i16);
        }
        asm volatile("cp.async.commit_group;" ::: "memory");
    };
    cpW(0, 0);

    const float* xpa = g_xT + (size_t)p * 65536 + tokbase + tok;         // dim 8c+p
    const float* xpb = g_xT + (size_t)(p + 4) * 65536 + tokbase + tok;   // dim 8c+p+4

    auto buildA = [&](unsigned aoff, float xa, float xb) {
        #pragma unroll
        for (int d2 = 0; d2 < 2; ++d2) {
            float xv = d2 ? xb : xa;
            int dim = p + d2 * 4;
            float ex = __expf(-xv);
            float s  = __fdividef(xv, 1.f + ex);            // silu
            float t5 = fmaf(xv, 5.f, 8.f);
            float cf = floorf(t5);
            int   ci = (int)cf;
            float u  = t5 - cf;
            float um = 1.f - u;
            float u2 = u * u, um2 = um * um;
            float b0 = um2 * um * (1.f / 6.f);
            float b3 = u2 * u * (1.f / 6.f);
            float b1 = fmaf(u2, fmaf(u, 0.5f, -1.f), 2.f / 3.f);
            float b2 = fmaf(um2, fmaf(um, 0.5f, -1.f), 2.f / 3.f);
            unsigned char* rowb = smem + aoff + (unsigned)tok * PITCH + dim * 28;
            #pragma unroll
            for (int z = 0; z < 7; ++z) ((unsigned*)rowb)[z] = 0u;      // zero 14 slots
            unsigned short* r16 = (unsigned short*)rowb;
            r16[13] = __half_as_ushort(__float2half_rn(s));
            int j0 = ci - 3;
            unsigned short h0 = __half_as_ushort(__float2half_rn(b0));
            unsigned short h1 = __half_as_ushort(__float2half_rn(b1));
            unsigned short h2 = __half_as_ushort(__float2half_rn(b2));
            unsigned short h3 = __half_as_ushort(__float2half_rn(b3));
            if ((unsigned)(j0 + 0) <= 12u) r16[j0 + 0] = h0;
            if ((unsigned)(j0 + 1) <= 12u) r16[j0 + 1] = h1;
            if ((unsigned)(j0 + 2) <= 12u) r16[j0 + 2] = h2;
            if ((unsigned)(j0 + 3) <= 12u) r16[j0 + 3] = h3;
        }
        // zero the 8 pad halves at row end (slots 112..119), once per row (d2==0 thread p==0 covers? no)
    };

    // zero tail pad of A rows once (slots 112..119 = 16 bytes at offset 224)
    // each thread owns its token row in both buffers
    if (p == 0) {
        *(uint4*)(smem + SM_A0 + (unsigned)tok * PITCH + 224) = make_uint4(0, 0, 0, 0);
        *(uint4*)(smem + SM_A1 + (unsigned)tok * PITCH + 224) = make_uint4(0, 0, 0, 0);
    }

    // prologue: A(0) + x pipeline (distance 2)
    float xaN, xbN;
    {
        float xa0 = __ldg(xpa), xb0 = __ldg(xpb);
        buildA(SM_A0, xa0, xb0);
        xaN = __ldg(xpa + 8u * 65536u);
        xbN = __ldg(xpb + 8u * 65536u);
    }

    for (int c = 0; c < NCHUNK; ++c) {
        const unsigned ab = sb + ((c & 1) ? SM_A1 : SM_A0);

        asm volatile("cp.async.wait_group 0;" ::: "memory");   // W(c) resident
        __syncthreads();                                       // A(c)+W(c) visible; buf free

        if (c + 1 < NCHUNK) cpW(c + 1, (c + 1) & 1);           // safe: last read at c-1

        // ---- MMA(c): 7 k-steps x 4 n16-groups (this warp's n-half) ----
        const unsigned wb = sb + SM_W + (c & 1) * WBUF + hOff;
        unsigned a[7][4];
        #pragma unroll
        for (int ks = 0; ks < 7; ++ks) LDSM_X4(a[ks], ab + paBase + ks * 32);
        #pragma unroll
        for (int ng = 0; ng < 4; ++ng) {
            const unsigned base = wb + ng * 16 * PITCH + pbBase;
            #pragma unroll
            for (int ks = 0; ks < 7; ++ks) {
                unsigned b[4];
                LDSM_X4(b, base + ks * 32);
                MMA16816(acc[ng * 2],     a[ks], b[0], b[1]);
                MMA16816(acc[ng * 2 + 1], a[ks], b[2], b[3]);
            }
        }

        // ---- x(c+2) loads, then build A(c+1) (overlaps MMA latency) ----
        float xa2 = 0.f, xb2 = 0.f;
        if (c + 2 < NCHUNK) {
            xa2 = __ldg(xpa + (size_t)(8 * (c + 2)) * 65536u);
            xb2 = __ldg(xpb + (size_t)(8 * (c + 2)) * 65536u);
        }
        if (c + 1 < NCHUNK)
            buildA(((c + 1) & 1) ? SM_A1 : SM_A0, xaN, xbN);
        xaN = xa2; xbN = xb2;
    }

    // ---------------- epilogue: LN (cross n-half) + gamma/beta + residual ----
    float s0 = 0.f, q0 = 0.f, s1 = 0.f, q1 = 0.f;
    #pragma unroll
    for (int t = 0; t < 8; ++t) {
        s0 += acc[t][0] + acc[t][1];
        q0 = fmaf(acc[t][0], acc[t][0], fmaf(acc[t][1], acc[t][1], q0));
        s1 += acc[t][2] + acc[t][3];
        q1 = fmaf(acc[t][2], acc[t][2], fmaf(acc[t][3], acc[t][3], q1));
    }
    #pragma unroll
    for (int m = 1; m <= 2; m <<= 1) {
        s0 += __shfl_xor_sync(0xffffffffu, s0, m);
        q0 += __shfl_xor_sync(0xffffffffu, q0, m);
        s1 += __shfl_xor_sync(0xffffffffu, s1, m);
        q1 += __shfl_xor_sync(0xffffffffu, q1, m);
    }
    // exchange halves via smem: epi[token][half] = (sum, sumsq)
    float2* epi = (float2*)(smem + SM_EPI);
    const int tr = g * 16 + (l >> 2);
    if ((l & 3) == 0) {
        epi[tr * 2 + h]       = make_float2(s0, q0);
        epi[(tr + 8) * 2 + h] = make_float2(s1, q1);
    }
    __syncthreads();
    float2 o0 = epi[tr * 2 + (h ^ 1)];
    float2 o1 = epi[(tr + 8) * 2 + (h ^ 1)];
    float mu0 = (s0 + o0.x) * (1.f / 128.f);
    float rs0 = rsqrtf(fmaf(q0 + o0.y, 1.f / 128.f, -mu0 * mu0) + LN_EPS);
    float mu1 = (s1 + o1.x) * (1.f / 128.f);
    float rs1 = rsqrtf(fmaf(q1 + o1.y, 1.f / 128.f, -mu1 * mu1) + LN_EPS);

    const int r0 = tokbase + tr;
    const int r1 = r0 + 8;
    const float* x0 = x + (size_t)r0 * 128;
    const float* x1 = x + (size_t)r1 * 128;
    float* out0 = out + (size_t)r0 * 128;
    float* out1 = out + (size_t)r1 * 128;
    #pragma unroll
    for (int t = 0; t < 8; ++t) {
        int n = h * 64 + (t >> 1) * 16 + (t & 1) * 8 + (l & 3) * 2;
        float4 gb = *(const float4*)(smem + SM_GB + n * 8);   // g[n],b[n],g[n+1],b[n+1]
        float2 xa = *(const float2*)(x0 + n);
        float2 xb = *(const float2*)(x1 + n);
        float2 oa, ob;
        oa.x = fmaf((acc[t][0] - mu0) * rs0, gb.x, gb.y) + xa.x;
        oa.y = fmaf((acc[t][1] - mu0) * rs0, gb.z, gb.w) + xa.y;
        ob.x = fmaf((acc[t][2] - mu1) * rs1, gb.x, gb.y) + xb.x;
        ob.y = fmaf((acc[t][3] - mu1) * rs1, gb.z, gb.w) + xb.y;
        *(float2*)(out0 + n) = oa;
        *(float2*)(out1 + n) = ob;
    }
}

// -------------------------------------------------------------------- launch
extern "C" void kernel_launch(void* const* d_in, const int* in_sizes, int n_in,
                              void* d_out, int out_size) {
    const float* x        = (const float*)d_in[0];
    const float* base_w   = (const float*)d_in[2];
    const float* spline_w = (const float*)d_in[3];
    const float* gamma    = (const float*)d_in[4];
    const float* beta     = (const float*)d_in[5];
    float* out            = (float*)d_out;

    dim3 tb(32, 8);
    transpose_x<<<dim3(2048, 4), tb>>>(x);
    prep_w<<<960, 256>>>(base_w, spline_w);
    cudaFuncSetAttribute(kan_mma, cudaFuncAttributeMaxDynamicSharedMemorySize, SM_TOT);
    kan_mma<<<NCTA, 256, SM_TOT>>>(x, gamma, beta, out);
}